// round 12
// baseline (speedup 1.0000x reference)
#include <cuda_runtime.h>

// x: (16, 2, 1024, 1024) fp32, 20 diffusion steps. Weights exact in fp32:
// hx = hy = 0.25, center = 0 -> one step == 0.25*(L+R+U+D).
// K=5 unscaled stages per pass (3 FADD/elem/stage), deferred exact scale
// 0.25^5 = 1/1024 at store. 4 passes.
// Round 12: RB=64 + __launch_bounds__(256,3) -> 576 blocks, 24 warps/SM
// (vs 16): +50% latency hiding for +7% halo work.
#define HH 1024
#define WW 1024
#define NPLANES 32
#define PLANE_ELEMS (HH * WW)
#define K 5
#define RB 64          // output rows per warp-band
#define NBANDS (HH / RB)        // 16
#define NSTRIP 9       // strip j input base = 112*j, window 128 cols
#define FINAL_SCALE (1.0f / 1024.0f)   // 0.25^K, exact power of two

__device__ float g_scratch[NPLANES * PLANE_ELEMS];

__device__ __forceinline__ int reflect_row(int i) {
    i = (i < 0) ? -i : i;
    return (i >= HH) ? (2 * HH - 2 - i) : i;
}

template<bool EDGEL, bool EDGER>
__device__ __forceinline__ void run_band(
    const float* __restrict__ sp, float* __restrict__ dp,
    int g, int r0, int lane)
{
    const int lo = EDGEL ? 0 : 2;
    const int hi = EDGER ? 31 : 29;
    const bool do_store = (lane >= lo && lane <= hi);
    const bool fixL = EDGEL && (lane == 0);
    const bool fixR = EDGER && (lane == 31);

    // Rolling window per stage s: a[s] = v_s[row-2], b[s] = v_s[row-1]
    // (v_s are UNSCALED partial sums: v_s = 4^s * u_s).
    float4 a[K], b[K];
#pragma unroll
    for (int s = 0; s < K; ++s) {
        a[s] = make_float4(0.f, 0.f, 0.f, 0.f);
        b[s] = make_float4(0.f, 0.f, 0.f, 0.f);
    }

    const int niter = RB + 2 * K;   // 74

    // Prefetch pipeline, depth 2 (reflect keeps all rows in-bounds).
    float4 p0 = ((const float4*)(sp + (size_t)reflect_row(r0 - K)     * WW))[g];
    float4 p1 = ((const float4*)(sp + (size_t)reflect_row(r0 - K + 1) * WW))[g];

#pragma unroll 2
    for (int m = 0; m < niter; ++m) {
        const int i = r0 - K + m;   // input row index for stage 0

        // Shuffle batch: operands are iteration-start state only.
        float lv[K], rv[K];
#pragma unroll
        for (int s = 0; s < K; ++s) {
            const float lu = __shfl_up_sync(0xffffffffu, b[s].w, 1);
            const float rd = __shfl_down_sync(0xffffffffu, b[s].x, 1);
            lv[s] = fixL ? b[s].y : lu;   // mirror col -1 -> col 1
            rv[s] = fixR ? b[s].z : rd;   // mirror col 1024 -> col 1022
        }

        float4 cur[K + 1];
        cur[0] = p0;
        p0 = p1;
        p1 = ((const float4*)(sp + (size_t)reflect_row(i + 2) * WW))[g];

#pragma unroll
        for (int s = 1; s <= K; ++s) {
            const float4 B = b[s - 1];    // center row (iter-start state)
            const float4 A = a[s - 1];    // up row     (iter-start state)
            const float4 D = cur[s - 1];  // down row   (fresh — consume last)

            // Unscaled stage: v' = L + R + U + D (3 FADD/elem, fresh-last).
            float4 h;
            h.x = (lv[s - 1] + B.y) + A.x;
            h.y = (B.x + B.z)       + A.y;
            h.z = (B.y + B.w)       + A.z;
            h.w = (B.z + rv[s - 1]) + A.w;

            float4 o;
            o.x = h.x + D.x;
            o.y = h.y + D.y;
            o.z = h.z + D.z;
            o.w = h.w + D.w;
            cur[s] = o;
        }

        // Final-stage row j = i - K is a band row exactly when m >= 2K.
        if (m >= 2 * K && do_store) {
            float4 o;
            o.x = cur[K].x * FINAL_SCALE;
            o.y = cur[K].y * FINAL_SCALE;
            o.z = cur[K].z * FINAL_SCALE;
            o.w = cur[K].w * FINAL_SCALE;
            ((float4*)(dp + (size_t)(i - K) * WW))[g] = o;
        }

#pragma unroll
        for (int s = 0; s < K; ++s) {
            a[s] = b[s];
            b[s] = cur[s];
        }
    }
}

__global__ __launch_bounds__(256, 3)
void fused_stencil(const float* __restrict__ src,
                   float* __restrict__ dst)
{
    const int strip = blockIdx.x;          // 0..8
    const int img   = blockIdx.y;          // 0..31
    const int band  = blockIdx.z * 8 + (threadIdx.x >> 5);  // 0..15
    const int lane  = threadIdx.x & 31;

    const float* sp = src + (size_t)img * PLANE_ELEMS;
    float*       dp = dst + (size_t)img * PLANE_ELEMS;

    const int g  = ((strip * 112) >> 2) + lane;   // lane's float4 column index
    const int r0 = band * RB;

    if (strip == 0) {
        run_band<true, false>(sp, dp, g, r0, lane);
    } else if (strip == NSTRIP - 1) {
        run_band<false, true>(sp, dp, g, r0, lane);
    } else {
        run_band<false, false>(sp, dp, g, r0, lane);
    }
}

extern "C" void kernel_launch(void* const* d_in, const int* in_sizes, int n_in,
                              void* d_out, int out_size)
{
    const float* x = (const float*)d_in[0];
    float* out = (float*)d_out;

    float* scratch = nullptr;
    cudaGetSymbolAddress((void**)&scratch, g_scratch);

    dim3 grid(NSTRIP, NPLANES, 2);   // 9 strips x 32 planes x 2 = 576 blocks
    dim3 block(256);                 // 8 warps = 8 row bands of 64 rows

    // 4 passes of 5 fused steps: x -> scratch -> out -> scratch -> out
    fused_stencil<<<grid, block>>>(x,       scratch);
    fused_stencil<<<grid, block>>>(scratch, out);
    fused_stencil<<<grid, block>>>(out,     scratch);
    fused_stencil<<<grid, block>>>(scratch, out);
}

// round 13
// speedup vs baseline: 1.0219x; 1.0219x over previous
#include <cuda_runtime.h>

// x: (16, 2, 1024, 1024) fp32, 20 diffusion steps. Weights exact in fp32:
// hx = hy = 0.25, center = 0 -> one step == 0.25*(L+R+U+D).
// Round 13: THREE passes K=7+7+6 (vs 4x5) -> 24% less DRAM traffic, now the
// binding resource (R11 ran at ~95% of achievable BW). FADD-only stages
// (3 FADD/elem/stage) keep K=7 register state under the 128 cap; deferred
// exact scale 0.25^K (power of two) applied once at store.
// Structure = R11: 8-warp blocks, warp-independent 128-col strips with 8-col
// overlap, shuffle batch, fresh-row-last chains, depth-2 prefetch,
// compile-time edge specialization.
#define HH 1024
#define WW 1024
#define NPLANES 32
#define PLANE_ELEMS (HH * WW)
#define RB 128         // output rows per warp-band
#define NSTRIP 9       // strip j input base = 112*j, window 128 cols

__device__ float g_scratch[NPLANES * PLANE_ELEMS];

__device__ __forceinline__ int reflect_row(int i) {
    i = (i < 0) ? -i : i;
    return (i >= HH) ? (2 * HH - 2 - i) : i;
}

template<int KK, bool EDGEL, bool EDGER>
__device__ __forceinline__ void run_band(
    const float* __restrict__ sp, float* __restrict__ dp,
    int g, int r0, int lane, float final_scale)
{
    // Interior strips keep lanes 2..29 (8-col halo/side covers KK<=8 stages
    // of 1-col/side garbage). Edge strips extend to the mirrored boundary.
    const int lo = EDGEL ? 0 : 2;
    const int hi = EDGER ? 31 : 29;
    const bool do_store = (lane >= lo && lane <= hi);
    const bool fixL = EDGEL && (lane == 0);
    const bool fixR = EDGER && (lane == 31);

    // Rolling window per stage s: a[s] = v_s[row-2], b[s] = v_s[row-1]
    // (v_s are UNSCALED partial sums: v_s = 4^s * u_s).
    float4 a[KK], b[KK];
#pragma unroll
    for (int s = 0; s < KK; ++s) {
        a[s] = make_float4(0.f, 0.f, 0.f, 0.f);
        b[s] = make_float4(0.f, 0.f, 0.f, 0.f);
    }

    const int niter = RB + 2 * KK;

    // Prefetch pipeline, depth 2 (reflect keeps all rows in-bounds).
    float4 p0 = ((const float4*)(sp + (size_t)reflect_row(r0 - KK)     * WW))[g];
    float4 p1 = ((const float4*)(sp + (size_t)reflect_row(r0 - KK + 1) * WW))[g];

    for (int m = 0; m < niter; ++m) {
        const int i = r0 - KK + m;   // input row index for stage 0

        // Shuffle batch: operands are iteration-start state only.
        float lv[KK], rv[KK];
#pragma unroll
        for (int s = 0; s < KK; ++s) {
            const float lu = __shfl_up_sync(0xffffffffu, b[s].w, 1);
            const float rd = __shfl_down_sync(0xffffffffu, b[s].x, 1);
            lv[s] = fixL ? b[s].y : lu;   // mirror col -1 -> col 1
            rv[s] = fixR ? b[s].z : rd;   // mirror col 1024 -> col 1022
        }

        float4 cur[KK + 1];
        cur[0] = p0;
        p0 = p1;
        p1 = ((const float4*)(sp + (size_t)reflect_row(i + 2) * WW))[g];

#pragma unroll
        for (int s = 1; s <= KK; ++s) {
            const float4 B = b[s - 1];    // center row (iter-start state)
            const float4 A = a[s - 1];    // up row     (iter-start state)
            const float4 D = cur[s - 1];  // down row   (fresh — consume last)

            // Unscaled stage: v' = L + R + U + D (3 FADD/elem, fresh-last).
            float4 h;
            h.x = (lv[s - 1] + B.y) + A.x;
            h.y = (B.x + B.z)       + A.y;
            h.z = (B.y + B.w)       + A.z;
            h.w = (B.z + rv[s - 1]) + A.w;

            float4 o;
            o.x = h.x + D.x;
            o.y = h.y + D.y;
            o.z = h.z + D.z;
            o.w = h.w + D.w;
            cur[s] = o;
        }

        // Final-stage row j = i - KK is a band row exactly when m >= 2*KK.
        if (m >= 2 * KK && do_store) {
            float4 o;
            o.x = cur[KK].x * final_scale;
            o.y = cur[KK].y * final_scale;
            o.z = cur[KK].z * final_scale;
            o.w = cur[KK].w * final_scale;
            ((float4*)(dp + (size_t)(i - KK) * WW))[g] = o;
        }

#pragma unroll
        for (int s = 0; s < KK; ++s) {
            a[s] = b[s];
            b[s] = cur[s];
        }
    }
}

template<int KK>
__global__ __launch_bounds__(256, 2)
void fused_stencil(const float* __restrict__ src,
                   float* __restrict__ dst,
                   float final_scale)
{
    const int strip = blockIdx.x;          // 0..8
    const int img   = blockIdx.y;          // 0..31
    const int warp  = threadIdx.x >> 5;    // band 0..7
    const int lane  = threadIdx.x & 31;

    const float* sp = src + (size_t)img * PLANE_ELEMS;
    float*       dp = dst + (size_t)img * PLANE_ELEMS;

    const int g  = ((strip * 112) >> 2) + lane;   // lane's float4 column index
    const int r0 = warp * RB;

    if (strip == 0) {
        run_band<KK, true, false>(sp, dp, g, r0, lane, final_scale);
    } else if (strip == NSTRIP - 1) {
        run_band<KK, false, true>(sp, dp, g, r0, lane, final_scale);
    } else {
        run_band<KK, false, false>(sp, dp, g, r0, lane, final_scale);
    }
}

extern "C" void kernel_launch(void* const* d_in, const int* in_sizes, int n_in,
                              void* d_out, int out_size)
{
    const float* x = (const float*)d_in[0];
    float* out = (float*)d_out;

    float* scratch = nullptr;
    cudaGetSymbolAddress((void**)&scratch, g_scratch);

    dim3 grid(NSTRIP, NPLANES);   // 9 strips x 32 planes = 288 blocks
    dim3 block(256);              // 8 warps = 8 row bands of 128 rows

    // 7 + 7 + 6 = 20 steps; d_out serves as intermediate (fully overwritten).
    // Deferred scales are exact powers of two: 0.25^7, 0.25^7, 0.25^6.
    fused_stencil<7><<<grid, block>>>(x,       out,     1.0f / 16384.0f);
    fused_stencil<7><<<grid, block>>>(out,     scratch, 1.0f / 16384.0f);
    fused_stencil<6><<<grid, block>>>(scratch, out,     1.0f / 4096.0f);
}

// round 14
// speedup vs baseline: 1.3771x; 1.3476x over previous
#include <cuda_runtime.h>

// x: (16, 2, 1024, 1024) fp32, 20 diffusion steps. Weights exact in fp32:
// hx = hy = 0.25, center = 0 -> one step == 0.25*(L+R+U+D).
// THREE passes K=7+7+6 (24% less DRAM traffic than 4x5; 4-pass scheme is at
// ~94% of achievable BW). FADD-only stages, deferred exact 0.25^K scale.
// Round 14 fix vs R13: #pragma unroll 2 on the row loop so the rotating
// register window renames instead of emitting 2K*4 MOVs/iter (R13's alu=39%),
// plus streaming stores (dst never re-read in-pass).
#define HH 1024
#define WW 1024
#define NPLANES 32
#define PLANE_ELEMS (HH * WW)
#define RB 128         // output rows per warp-band
#define NSTRIP 9       // strip j input base = 112*j, window 128 cols

__device__ float g_scratch[NPLANES * PLANE_ELEMS];

__device__ __forceinline__ int reflect_row(int i) {
    i = (i < 0) ? -i : i;
    return (i >= HH) ? (2 * HH - 2 - i) : i;
}

__device__ __forceinline__ void stcs4(float* p, float4 v) {
    asm volatile("st.global.cs.v4.f32 [%0], {%1, %2, %3, %4};"
                 :: "l"(p), "f"(v.x), "f"(v.y), "f"(v.z), "f"(v.w)
                 : "memory");
}

template<int KK, bool EDGEL, bool EDGER>
__device__ __forceinline__ void run_band(
    const float* __restrict__ sp, float* __restrict__ dp,
    int g, int r0, int lane, float final_scale)
{
    // Interior strips keep lanes 2..29 (8-col halo/side covers KK<=8 stages
    // of 1-col/side garbage). Edge strips extend to the mirrored boundary.
    const int lo = EDGEL ? 0 : 2;
    const int hi = EDGER ? 31 : 29;
    const bool do_store = (lane >= lo && lane <= hi);
    const bool fixL = EDGEL && (lane == 0);
    const bool fixR = EDGER && (lane == 31);

    // Rolling window per stage s: a[s] = v_s[row-2], b[s] = v_s[row-1]
    // (v_s are UNSCALED partial sums: v_s = 4^s * u_s).
    float4 a[KK], b[KK];
#pragma unroll
    for (int s = 0; s < KK; ++s) {
        a[s] = make_float4(0.f, 0.f, 0.f, 0.f);
        b[s] = make_float4(0.f, 0.f, 0.f, 0.f);
    }

    const int niter = RB + 2 * KK;   // 142 (K=7) / 140 (K=6) — even

    // Prefetch pipeline, depth 2 (reflect keeps all rows in-bounds).
    float4 p0 = ((const float4*)(sp + (size_t)reflect_row(r0 - KK)     * WW))[g];
    float4 p1 = ((const float4*)(sp + (size_t)reflect_row(r0 - KK + 1) * WW))[g];

#pragma unroll 2
    for (int m = 0; m < niter; ++m) {
        const int i = r0 - KK + m;   // input row index for stage 0

        // Shuffle batch: operands are iteration-start state only.
        float lv[KK], rv[KK];
#pragma unroll
        for (int s = 0; s < KK; ++s) {
            const float lu = __shfl_up_sync(0xffffffffu, b[s].w, 1);
            const float rd = __shfl_down_sync(0xffffffffu, b[s].x, 1);
            lv[s] = fixL ? b[s].y : lu;   // mirror col -1 -> col 1
            rv[s] = fixR ? b[s].z : rd;   // mirror col 1024 -> col 1022
        }

        float4 cur[KK + 1];
        cur[0] = p0;
        p0 = p1;
        p1 = ((const float4*)(sp + (size_t)reflect_row(i + 2) * WW))[g];

#pragma unroll
        for (int s = 1; s <= KK; ++s) {
            const float4 B = b[s - 1];    // center row (iter-start state)
            const float4 A = a[s - 1];    // up row     (iter-start state)
            const float4 D = cur[s - 1];  // down row   (fresh — consume last)

            // Unscaled stage: v' = L + R + U + D (3 FADD/elem, fresh-last).
            float4 h;
            h.x = (lv[s - 1] + B.y) + A.x;
            h.y = (B.x + B.z)       + A.y;
            h.z = (B.y + B.w)       + A.z;
            h.w = (B.z + rv[s - 1]) + A.w;

            float4 o;
            o.x = h.x + D.x;
            o.y = h.y + D.y;
            o.z = h.z + D.z;
            o.w = h.w + D.w;
            cur[s] = o;
        }

        // Final-stage row j = i - KK is a band row exactly when m >= 2*KK.
        if (m >= 2 * KK && do_store) {
            float4 o;
            o.x = cur[KK].x * final_scale;
            o.y = cur[KK].y * final_scale;
            o.z = cur[KK].z * final_scale;
            o.w = cur[KK].w * final_scale;
            stcs4(dp + (size_t)(i - KK) * WW + 4 * g, o);
        }

#pragma unroll
        for (int s = 0; s < KK; ++s) {
            a[s] = b[s];
            b[s] = cur[s];
        }
    }
}

template<int KK>
__global__ __launch_bounds__(256, 2)
void fused_stencil(const float* __restrict__ src,
                   float* __restrict__ dst,
                   float final_scale)
{
    const int strip = blockIdx.x;          // 0..8
    const int img   = blockIdx.y;          // 0..31
    const int warp  = threadIdx.x >> 5;    // band 0..7
    const int lane  = threadIdx.x & 31;

    const float* sp = src + (size_t)img * PLANE_ELEMS;
    float*       dp = dst + (size_t)img * PLANE_ELEMS;

    const int g  = ((strip * 112) >> 2) + lane;   // lane's float4 column index
    const int r0 = warp * RB;

    if (strip == 0) {
        run_band<KK, true, false>(sp, dp, g, r0, lane, final_scale);
    } else if (strip == NSTRIP - 1) {
        run_band<KK, false, true>(sp, dp, g, r0, lane, final_scale);
    } else {
        run_band<KK, false, false>(sp, dp, g, r0, lane, final_scale);
    }
}

extern "C" void kernel_launch(void* const* d_in, const int* in_sizes, int n_in,
                              void* d_out, int out_size)
{
    const float* x = (const float*)d_in[0];
    float* out = (float*)d_out;

    float* scratch = nullptr;
    cudaGetSymbolAddress((void**)&scratch, g_scratch);

    dim3 grid(NSTRIP, NPLANES);   // 9 strips x 32 planes = 288 blocks
    dim3 block(256);              // 8 warps = 8 row bands of 128 rows

    // 7 + 7 + 6 = 20 steps; d_out serves as intermediate (fully overwritten).
    // Deferred scales are exact powers of two: 0.25^7, 0.25^7, 0.25^6.
    fused_stencil<7><<<grid, block>>>(x,       out,     1.0f / 16384.0f);
    fused_stencil<7><<<grid, block>>>(out,     scratch, 1.0f / 16384.0f);
    fused_stencil<6><<<grid, block>>>(scratch, out,     1.0f / 4096.0f);
}